// round 7
// baseline (speedup 1.0000x reference)
#include <cuda_runtime.h>
#include <cstdint>

#define D 8192
#define THREADS 512
#define PER_THREAD (D / THREADS)        // 16 scalars per thread
#define NWARPS (THREADS / 32)           // 16
#define BUF 1024                        // candidate buffer (floats)

// Read-only sparsemax: output has been pre-zeroed by a memset node; this kernel
// reads x, computes tau per row, and writes ONLY the support (x > tau).
__global__ __launch_bounds__(THREADS, 3)
void sparsemax_kernel(const float* __restrict__ x, float* __restrict__ out) {
    __shared__ float sbuf[BUF];          // candidates > max-1
    __shared__ float swarp[NWARPS];      // block max scratch
    __shared__ float sredf[NWARPS];      // fallback sum scratch
    __shared__ int   sredk[NWARPS];      // fallback count scratch
    __shared__ int   s_cnt;
    __shared__ float s_tau;
    __shared__ int   s_k;

    const int row = blockIdx.x;
    const int tid = threadIdx.x;
    const int lid = tid & 31;
    const float4* __restrict__ xin = reinterpret_cast<const float4*>(x + (size_t)row * D);

    if (tid == 0) s_cnt = 0;

    // ---- load 16 values into registers (4x independent LDG.128, streaming) ----
    float4 c0 = __ldcs(&xin[tid]);
    float4 c1 = __ldcs(&xin[tid + THREADS]);
    float4 c2 = __ldcs(&xin[tid + 2 * THREADS]);
    float4 c3 = __ldcs(&xin[tid + 3 * THREADS]);

    // ---- block max reduction ----
    float m = fmaxf(fmaxf(fmaxf(c0.x, c0.y), fmaxf(c0.z, c0.w)),
                    fmaxf(fmaxf(c1.x, c1.y), fmaxf(c1.z, c1.w)));
    m = fmaxf(m, fmaxf(fmaxf(c2.x, c2.y), fmaxf(c2.z, c2.w)));
    m = fmaxf(m, fmaxf(fmaxf(c3.x, c3.y), fmaxf(c3.z, c3.w)));
    #pragma unroll
    for (int o = 16; o > 0; o >>= 1)
        m = fmaxf(m, __shfl_xor_sync(0xffffffffu, m, o));
    if (lid == 0) swarp[tid >> 5] = m;
    __syncthreads();   // also covers s_cnt = 0

    float mm = swarp[lid & (NWARPS - 1)];
    #pragma unroll
    for (int o = NWARPS / 2; o > 0; o >>= 1)
        mm = fmaxf(mm, __shfl_xor_sync(0xffffffffu, mm, o));
    const float thr = mm - 1.0f;         // valid lower bound on tau*

    // ---- gather candidates {x > thr} (rare for gaussian rows) ----
    {
        float vals[PER_THREAD] = {c0.x, c0.y, c0.z, c0.w, c1.x, c1.y, c1.z, c1.w,
                                  c2.x, c2.y, c2.z, c2.w, c3.x, c3.y, c3.z, c3.w};
        #pragma unroll
        for (int i = 0; i < PER_THREAD; i++) {
            if (vals[i] > thr) {
                int p = atomicAdd(&s_cnt, 1);
                if (p < BUF) sbuf[p] = vals[i];
            }
        }
    }
    __syncthreads();
    const int cnt = s_cnt;

    if (cnt <= BUF) {
        // ---- Michelot fixed-point on the tiny candidate set (warp 0) ----
        if (tid < 32) {
            float tau = thr;
            int prev = -1;
            for (int it = 0; it < cnt + 2; it++) {
                float s = 0.0f; int k = 0;
                for (int j = tid; j < cnt; j += 32) {
                    float v = sbuf[j];
                    if (v > tau) { s += v; k++; }
                }
                #pragma unroll
                for (int o = 16; o > 0; o >>= 1) {
                    s += __shfl_xor_sync(0xffffffffu, s, o);
                    k += __shfl_xor_sync(0xffffffffu, k, o);
                }
                tau = (s - 1.0f) / (float)k;
                if (k == prev) break;    // active set stable -> fixed point
                prev = k;
            }
            if (tid == 0) s_tau = tau;
        }
        __syncthreads();
    } else {
        // ---- Fallback: block-wide Michelot over register values ----
        float tau = thr;
        int prev = -1;
        for (int it = 0; it < D + 2; it++) {
            float s = 0.0f; int k = 0;
            float vals[PER_THREAD] = {c0.x, c0.y, c0.z, c0.w, c1.x, c1.y, c1.z, c1.w,
                                      c2.x, c2.y, c2.z, c2.w, c3.x, c3.y, c3.z, c3.w};
            #pragma unroll
            for (int i = 0; i < PER_THREAD; i++)
                if (vals[i] > tau) { s += vals[i]; k++; }
            #pragma unroll
            for (int o = 16; o > 0; o >>= 1) {
                s += __shfl_xor_sync(0xffffffffu, s, o);
                k += __shfl_xor_sync(0xffffffffu, k, o);
            }
            if (lid == 0) { sredf[tid >> 5] = s; sredk[tid >> 5] = k; }
            __syncthreads();
            if (tid == 0) {
                float S = 0.0f; int K = 0;
                #pragma unroll
                for (int w = 0; w < NWARPS; w++) { S += sredf[w]; K += sredk[w]; }
                s_tau = (S - 1.0f) / (float)K;
                s_k = K;
            }
            __syncthreads();
            tau = s_tau;
            int K = s_k;
            if (K == prev) break;
            prev = K;
        }
        __syncthreads();
    }

    // ---- sparse write: only support elements (out pre-zeroed by memset) ----
    const float tau = s_tau;
    float* __restrict__ orow = out + (size_t)row * D;
    {
        float vals[PER_THREAD] = {c0.x, c0.y, c0.z, c0.w, c1.x, c1.y, c1.z, c1.w,
                                  c2.x, c2.y, c2.z, c2.w, c3.x, c3.y, c3.z, c3.w};
        #pragma unroll
        for (int k = 0; k < 4; k++) {
            #pragma unroll
            for (int j = 0; j < 4; j++) {
                float v = vals[k * 4 + j];
                if (v > tau)
                    orow[4 * (tid + k * THREADS) + j] = v - tau;
            }
        }
    }
}

extern "C" void kernel_launch(void* const* d_in, const int* in_sizes, int n_in,
                              void* d_out, int out_size) {
    const float* x = (const float*)d_in[0];
    float* out = (float*)d_out;
    const int rows = in_sizes[0] / D;   // 8192

    // 1) zero the output at dedicated write bandwidth (graph-capturable memset node)
    cudaMemsetAsync(d_out, 0, (size_t)out_size * sizeof(float));

    // 2) read-only sparsemax with sparse scatter of the support
    sparsemax_kernel<<<rows, THREADS>>>(x, out);
}

// round 8
// speedup vs baseline: 1.0128x; 1.0128x over previous
#include <cuda_runtime.h>
#include <cstdint>

#define D 8192
#define THREADS 512
#define NWARPS (THREADS / 32)           // 16
#define BUF 1024                        // candidate buffer (floats)
#define ROW_BYTES (D * 4)               // 32768

// ---- PTX helpers (sm_90+/sm_103a) ----
__device__ __forceinline__ uint32_t smem_u32(const void* p) {
    return (uint32_t)__cvta_generic_to_shared(p);
}
__device__ __forceinline__ void mbar_init(uint32_t mbar, uint32_t count) {
    asm volatile("mbarrier.init.shared::cta.b64 [%0], %1;" :: "r"(mbar), "r"(count) : "memory");
}
__device__ __forceinline__ void mbar_expect_tx(uint32_t mbar, uint32_t bytes) {
    asm volatile("mbarrier.arrive.expect_tx.shared::cta.b64 _, [%0], %1;"
                 :: "r"(mbar), "r"(bytes) : "memory");
}
__device__ __forceinline__ void tma_1d_g2s(uint32_t dst_smem, const void* src_gmem,
                                           uint32_t bytes, uint32_t mbar) {
    asm volatile("cp.async.bulk.shared::cluster.global.mbarrier::complete_tx::bytes "
                 "[%0], [%1], %2, [%3];"
                 :: "r"(dst_smem), "l"(src_gmem), "r"(bytes), "r"(mbar) : "memory");
}
__device__ __forceinline__ void l2_prefetch_bulk(const void* src_gmem, uint32_t bytes) {
    asm volatile("cp.async.bulk.prefetch.L2.global [%0], %1;"
                 :: "l"(src_gmem), "r"(bytes) : "memory");
}
__device__ __forceinline__ void mbar_wait(uint32_t mbar, uint32_t parity) {
    uint32_t done;
    asm volatile("{\n\t.reg .pred p;\n\t"
                 "mbarrier.try_wait.parity.acquire.cta.shared::cta.b64 p, [%1], %2;\n\t"
                 "selp.b32 %0, 1, 0, p;\n\t}"
                 : "=r"(done) : "r"(mbar), "r"(parity) : "memory");
    if (!done) {
        asm volatile("{\n\t.reg .pred P1;\n"
                     "WL_%=:\n\t"
                     "mbarrier.try_wait.parity.acquire.cta.shared::cta.b64 P1, [%0], %1, 0x989680;\n\t"
                     "@P1 bra.uni WD_%=;\n\t"
                     "bra.uni WL_%=;\n"
                     "WD_%=:\n\t}"
                     :: "r"(mbar), "r"(parity) : "memory");
    }
}

extern __shared__ float srow[];          // dynamic: 2 * D floats = 64 KB (double buffer)

// Persistent read-only sparsemax: out pre-zeroed by memset node; this kernel
// streams rows via TMA double-buffer + L2 prefetch, computes tau per row, and
// scatters ONLY the support (x > tau) — a handful of STG.32 per row.
__global__ __launch_bounds__(THREADS, 3)
void sparsemax_kernel(const float* __restrict__ x, float* __restrict__ out, int nrows) {
    __shared__ float sbuf[BUF];          // candidates > max-1
    __shared__ float swarp[NWARPS];      // block max scratch
    __shared__ float sredf[NWARPS];      // fallback sum scratch
    __shared__ int   sredk[NWARPS];      // fallback count scratch
    __shared__ int   s_cnt;
    __shared__ float s_tau;
    __shared__ int   s_k;
    __shared__ __align__(8) uint64_t mbar_storage[2];

    const int tid = threadIdx.x;
    const int lid = tid & 31;
    const int stride = gridDim.x;
    int r = blockIdx.x;
    if (r >= nrows) return;

    const uint32_t mb0 = smem_u32(&mbar_storage[0]);
    const uint32_t mb1 = smem_u32(&mbar_storage[1]);
    const uint32_t ba0 = smem_u32(&srow[0]);
    const uint32_t ba1 = smem_u32(&srow[D]);

    if (tid == 0) {
        mbar_init(mb0, 1);
        mbar_init(mb1, 1);
        s_cnt = 0;
        asm volatile("fence.mbarrier_init.release.cluster;" ::: "memory");
    }
    __syncthreads();

    // ---- prologue: TMA row r into buffer 0; L2-prefetch row r+stride ----
    if (tid == 0) {
        mbar_expect_tx(mb0, ROW_BYTES);
        tma_1d_g2s(ba0, x + (size_t)r * D, ROW_BYTES, mb0);
        long long r1 = (long long)r + stride;
        if (r1 < nrows) l2_prefetch_bulk(x + (size_t)r1 * D, ROW_BYTES);
    }

    int cur = 0;
    uint32_t ph0 = 0u, ph1 = 0u;

    while (true) {
        const int rn = r + stride;
        const bool has_next = (rn < nrows);

        // ---- issue TMA for next row (likely L2-hit) + L2 prefetch 2 rows ahead ----
        if (tid == 0) {
            if (has_next) {
                const uint32_t mbn = (cur == 0) ? mb1 : mb0;
                const uint32_t ban = (cur == 0) ? ba1 : ba0;
                mbar_expect_tx(mbn, ROW_BYTES);
                tma_1d_g2s(ban, x + (size_t)rn * D, ROW_BYTES, mbn);
            }
            long long r2 = (long long)r + 2LL * stride;
            if (r2 < nrows) l2_prefetch_bulk(x + (size_t)r2 * D, ROW_BYTES);
        }

        // ---- wait for current buffer, consume into registers ----
        if (cur == 0) { mbar_wait(mb0, ph0); ph0 ^= 1u; }
        else          { mbar_wait(mb1, ph1); ph1 ^= 1u; }

        const float4* sp = reinterpret_cast<const float4*>(srow + (size_t)cur * D);
        float4 c0 = sp[tid];
        float4 c1 = sp[tid + THREADS];
        float4 c2 = sp[tid + 2 * THREADS];
        float4 c3 = sp[tid + 3 * THREADS];
        __syncthreads();   // all threads done reading buf[cur] -> free for next issue

        // ---- max reduction ----
        float m = fmaxf(fmaxf(fmaxf(c0.x, c0.y), fmaxf(c0.z, c0.w)),
                        fmaxf(fmaxf(c1.x, c1.y), fmaxf(c1.z, c1.w)));
        m = fmaxf(m, fmaxf(fmaxf(c2.x, c2.y), fmaxf(c2.z, c2.w)));
        m = fmaxf(m, fmaxf(fmaxf(c3.x, c3.y), fmaxf(c3.z, c3.w)));
        #pragma unroll
        for (int o = 16; o > 0; o >>= 1)
            m = fmaxf(m, __shfl_xor_sync(0xffffffffu, m, o));
        if (lid == 0) swarp[tid >> 5] = m;
        __syncthreads();

        float mm = swarp[lid & (NWARPS - 1)];
        #pragma unroll
        for (int o = NWARPS / 2; o > 0; o >>= 1)
            mm = fmaxf(mm, __shfl_xor_sync(0xffffffffu, mm, o));
        const float thr = mm - 1.0f;     // valid lower bound on tau*

        // ---- gather candidates {x > thr} (rare for gaussian rows) ----
        {
            float vals[16] = {c0.x, c0.y, c0.z, c0.w, c1.x, c1.y, c1.z, c1.w,
                              c2.x, c2.y, c2.z, c2.w, c3.x, c3.y, c3.z, c3.w};
            #pragma unroll
            for (int i = 0; i < 16; i++) {
                if (vals[i] > thr) {
                    int p = atomicAdd(&s_cnt, 1);
                    if (p < BUF) sbuf[p] = vals[i];
                }
            }
        }
        __syncthreads();
        const int cnt = s_cnt;

        if (cnt <= BUF) {
            // ---- Michelot fixed-point on the tiny candidate set (warp 0) ----
            if (tid < 32) {
                float tau = thr;
                int prev = -1;
                for (int it = 0; it < cnt + 2; it++) {
                    float s = 0.0f; int k = 0;
                    for (int j = tid; j < cnt; j += 32) {
                        float v = sbuf[j];
                        if (v > tau) { s += v; k++; }
                    }
                    #pragma unroll
                    for (int o = 16; o > 0; o >>= 1) {
                        s += __shfl_xor_sync(0xffffffffu, s, o);
                        k += __shfl_xor_sync(0xffffffffu, k, o);
                    }
                    tau = (s - 1.0f) / (float)k;
                    if (k == prev) break;   // active set stable -> fixed point
                    prev = k;
                }
                if (tid == 0) s_tau = tau;
            }
            __syncthreads();
        } else {
            // ---- Fallback: block-wide Michelot over register values ----
            float tau = thr;
            int prev = -1;
            for (int it = 0; it < D + 2; it++) {
                float s = 0.0f; int k = 0;
                float vals[16] = {c0.x, c0.y, c0.z, c0.w, c1.x, c1.y, c1.z, c1.w,
                                  c2.x, c2.y, c2.z, c2.w, c3.x, c3.y, c3.z, c3.w};
                #pragma unroll
                for (int i = 0; i < 16; i++)
                    if (vals[i] > tau) { s += vals[i]; k++; }
                #pragma unroll
                for (int o = 16; o > 0; o >>= 1) {
                    s += __shfl_xor_sync(0xffffffffu, s, o);
                    k += __shfl_xor_sync(0xffffffffu, k, o);
                }
                if (lid == 0) { sredf[tid >> 5] = s; sredk[tid >> 5] = k; }
                __syncthreads();
                if (tid == 0) {
                    float S = 0.0f; int K = 0;
                    #pragma unroll
                    for (int w = 0; w < NWARPS; w++) { S += sredf[w]; K += sredk[w]; }
                    s_tau = (S - 1.0f) / (float)K;
                    s_k = K;
                }
                __syncthreads();
                tau = s_tau;
                int K = s_k;
                if (K == prev) break;
                prev = K;
            }
            __syncthreads();
        }

        if (tid == 0) s_cnt = 0;   // next gather is >=2 barriers away

        // ---- sparse scatter: only support elements (out pre-zeroed) ----
        {
            const float tau = s_tau;
            float* __restrict__ orow = out + (size_t)r * D;
            float vals[16] = {c0.x, c0.y, c0.z, c0.w, c1.x, c1.y, c1.z, c1.w,
                              c2.x, c2.y, c2.z, c2.w, c3.x, c3.y, c3.z, c3.w};
            #pragma unroll
            for (int k = 0; k < 4; k++) {
                #pragma unroll
                for (int j = 0; j < 4; j++) {
                    float v = vals[k * 4 + j];
                    if (v > tau)
                        orow[4 * (tid + k * THREADS) + j] = v - tau;
                }
            }
        }

        if (!has_next) break;
        cur ^= 1;
        r = rn;
    }
}

extern "C" void kernel_launch(void* const* d_in, const int* in_sizes, int n_in,
                              void* d_out, int out_size) {
    const float* x = (const float*)d_in[0];
    float* out = (float*)d_out;
    const int rows = in_sizes[0] / D;   // 8192

    const int dyn_smem = 2 * D * (int)sizeof(float);   // 64 KB double buffer
    cudaFuncSetAttribute(sparsemax_kernel,
                         cudaFuncAttributeMaxDynamicSharedMemorySize, dyn_smem);

    int dev = 0;
    cudaGetDevice(&dev);
    int nsm = 148;
    cudaDeviceGetAttribute(&nsm, cudaDevAttrMultiProcessorCount, dev);
    int grid = nsm * 3;                 // 3 CTAs/SM, persistent pipeline
    if (grid > rows) grid = rows;

    // 1) zero output at dedicated write bandwidth (graph-capturable memset node)
    cudaMemsetAsync(d_out, 0, (size_t)out_size * sizeof(float));
    // 2) persistent read-only sparsemax, scatters support only (ordered after memset)
    sparsemax_kernel<<<grid, THREADS, dyn_smem>>>(x, out, rows);
}

// round 9
// speedup vs baseline: 1.1367x; 1.1224x over previous
#include <cuda_runtime.h>
#include <cstdint>

#define D 8192
#define THREADS 512
#define NWARPS (THREADS / 32)           // 16
#define BUF 1024                        // candidate buffer (floats)
#define ROW_BYTES (D * 4)               // 32768

// ---- PTX helpers (sm_90+/sm_103a) ----
__device__ __forceinline__ uint32_t smem_u32(const void* p) {
    return (uint32_t)__cvta_generic_to_shared(p);
}
__device__ __forceinline__ void mbar_init(uint32_t mbar, uint32_t count) {
    asm volatile("mbarrier.init.shared::cta.b64 [%0], %1;" :: "r"(mbar), "r"(count) : "memory");
}
__device__ __forceinline__ void mbar_expect_tx(uint32_t mbar, uint32_t bytes) {
    asm volatile("mbarrier.arrive.expect_tx.shared::cta.b64 _, [%0], %1;"
                 :: "r"(mbar), "r"(bytes) : "memory");
}
__device__ __forceinline__ void tma_1d_g2s(uint32_t dst_smem, const void* src_gmem,
                                           uint32_t bytes, uint32_t mbar) {
    asm volatile("cp.async.bulk.shared::cluster.global.mbarrier::complete_tx::bytes "
                 "[%0], [%1], %2, [%3];"
                 :: "r"(dst_smem), "l"(src_gmem), "r"(bytes), "r"(mbar) : "memory");
}
__device__ __forceinline__ void l2_prefetch_bulk(const void* src_gmem, uint32_t bytes) {
    asm volatile("cp.async.bulk.prefetch.L2.global [%0], %1;"
                 :: "l"(src_gmem), "r"(bytes) : "memory");
}
__device__ __forceinline__ void mbar_wait(uint32_t mbar, uint32_t parity) {
    uint32_t done;
    asm volatile("{\n\t.reg .pred p;\n\t"
                 "mbarrier.try_wait.parity.acquire.cta.shared::cta.b64 p, [%1], %2;\n\t"
                 "selp.b32 %0, 1, 0, p;\n\t}"
                 : "=r"(done) : "r"(mbar), "r"(parity) : "memory");
    if (!done) {
        asm volatile("{\n\t.reg .pred P1;\n"
                     "WL_%=:\n\t"
                     "mbarrier.try_wait.parity.acquire.cta.shared::cta.b64 P1, [%0], %1, 0x989680;\n\t"
                     "@P1 bra.uni WD_%=;\n\t"
                     "bra.uni WL_%=;\n"
                     "WD_%=:\n\t}"
                     :: "r"(mbar), "r"(parity) : "memory");
    }
}

extern __shared__ float srow[];          // dynamic: 2 * D floats = 64 KB (double buffer)

#define GATHER1(v) do { if ((v) > thr) { int _p = atomicAdd(&s_cnt, 1); \
                        if (_p < BUF) sbuf[_p] = (v); } } while (0)

__global__ __launch_bounds__(THREADS, 3)
void sparsemax_kernel(const float* __restrict__ x, float* __restrict__ out, int nrows) {
    __shared__ float sbuf[BUF];          // candidates > max-1
    __shared__ float swarp[NWARPS];      // block max scratch
    __shared__ float sredf[NWARPS];      // fallback sum scratch
    __shared__ int   sredk[NWARPS];      // fallback count scratch
    __shared__ int   s_cnt;
    __shared__ float s_tau;
    __shared__ int   s_k;
    __shared__ __align__(8) uint64_t mbar_storage[2];

    const int tid = threadIdx.x;
    const int lid = tid & 31;
    const int stride = gridDim.x;
    int r = blockIdx.x;
    if (r >= nrows) return;

    const uint32_t mb0 = smem_u32(&mbar_storage[0]);
    const uint32_t mb1 = smem_u32(&mbar_storage[1]);
    const uint32_t ba0 = smem_u32(&srow[0]);
    const uint32_t ba1 = smem_u32(&srow[D]);

    if (tid == 0) {
        mbar_init(mb0, 1);
        mbar_init(mb1, 1);
        s_cnt = 0;
        asm volatile("fence.mbarrier_init.release.cluster;" ::: "memory");
    }
    __syncthreads();

    // ---- prologue: TMA row r into buffer 0; L2-prefetch row r+stride ----
    if (tid == 0) {
        mbar_expect_tx(mb0, ROW_BYTES);
        tma_1d_g2s(ba0, x + (size_t)r * D, ROW_BYTES, mb0);
        long long r1 = (long long)r + stride;
        if (r1 < nrows) l2_prefetch_bulk(x + (size_t)r1 * D, ROW_BYTES);
    }

    int cur = 0;
    uint32_t ph0 = 0u, ph1 = 0u;

    while (true) {
        const int rn = r + stride;
        const bool has_next = (rn < nrows);

        // ---- issue TMA for next row (likely L2-hit) + L2 prefetch 2 rows ahead ----
        if (tid == 0) {
            if (has_next) {
                const uint32_t mbn = (cur == 0) ? mb1 : mb0;
                const uint32_t ban = (cur == 0) ? ba1 : ba0;
                mbar_expect_tx(mbn, ROW_BYTES);
                tma_1d_g2s(ban, x + (size_t)rn * D, ROW_BYTES, mbn);
            }
            long long r2 = (long long)r + 2LL * stride;
            if (r2 < nrows) l2_prefetch_bulk(x + (size_t)r2 * D, ROW_BYTES);
        }

        // ---- wait for current buffer, consume into registers ----
        if (cur == 0) { mbar_wait(mb0, ph0); ph0 ^= 1u; }
        else          { mbar_wait(mb1, ph1); ph1 ^= 1u; }

        const float4* sp = reinterpret_cast<const float4*>(srow + (size_t)cur * D);
        float4 c0 = sp[tid];
        float4 c1 = sp[tid + THREADS];
        float4 c2 = sp[tid + 2 * THREADS];
        float4 c3 = sp[tid + 3 * THREADS];

        // ---- per-thread local max (data-depends on ALL 16 values) ----
        float m_local = fmaxf(fmaxf(fmaxf(c0.x, c0.y), fmaxf(c0.z, c0.w)),
                              fmaxf(fmaxf(c1.x, c1.y), fmaxf(c1.z, c1.w)));
        m_local = fmaxf(m_local, fmaxf(fmaxf(c2.x, c2.y), fmaxf(c2.z, c2.w)));
        m_local = fmaxf(m_local, fmaxf(fmaxf(c3.x, c3.y), fmaxf(c3.z, c3.w)));

        float m = m_local;
        #pragma unroll
        for (int o = 16; o > 0; o >>= 1)
            m = fmaxf(m, __shfl_xor_sync(0xffffffffu, m, o));
        if (lid == 0) swarp[tid >> 5] = m;
        // BARRIER 1: merged — every lane's m depends on all its LDS data, so
        // arrival implies buffer[cur] fully consumed; also publishes swarp.
        __syncthreads();

        float mm = swarp[lid & (NWARPS - 1)];
        #pragma unroll
        for (int o = NWARPS / 2; o > 0; o >>= 1)
            mm = fmaxf(mm, __shfl_xor_sync(0xffffffffu, mm, o));
        const float thr = mm - 1.0f;     // valid lower bound on tau*

        // ---- gather candidates: only ~15/512 threads pass the guard ----
        if (m_local > thr) {
            GATHER1(c0.x); GATHER1(c0.y); GATHER1(c0.z); GATHER1(c0.w);
            GATHER1(c1.x); GATHER1(c1.y); GATHER1(c1.z); GATHER1(c1.w);
            GATHER1(c2.x); GATHER1(c2.y); GATHER1(c2.z); GATHER1(c2.w);
            GATHER1(c3.x); GATHER1(c3.y); GATHER1(c3.z); GATHER1(c3.w);
        }
        __syncthreads();                 // BARRIER 2
        const int cnt = s_cnt;

        if (cnt <= BUF) {
            // ---- Michelot fixed-point on the tiny candidate set (warp 0) ----
            if (tid < 32) {
                float tau = thr;
                int prev = -1;
                for (int it = 0; it < cnt + 2; it++) {
                    float s = 0.0f; int k = 0;
                    for (int j = tid; j < cnt; j += 32) {
                        float v = sbuf[j];
                        if (v > tau) { s += v; k++; }
                    }
                    #pragma unroll
                    for (int o = 16; o > 0; o >>= 1) {
                        s += __shfl_xor_sync(0xffffffffu, s, o);
                        k += __shfl_xor_sync(0xffffffffu, k, o);
                    }
                    tau = (s - 1.0f) / (float)k;
                    if (k == prev) break;   // active set stable -> fixed point
                    prev = k;
                }
                if (tid == 0) s_tau = tau;
            }
        } else {
            // ---- Fallback: block-wide Michelot over register values ----
            float tau = thr;
            int prev = -1;
            for (int it = 0; it < D + 2; it++) {
                float s = 0.0f; int k = 0;
                #define ACC(v) do { if ((v) > tau) { s += (v); k++; } } while (0)
                ACC(c0.x); ACC(c0.y); ACC(c0.z); ACC(c0.w);
                ACC(c1.x); ACC(c1.y); ACC(c1.z); ACC(c1.w);
                ACC(c2.x); ACC(c2.y); ACC(c2.z); ACC(c2.w);
                ACC(c3.x); ACC(c3.y); ACC(c3.z); ACC(c3.w);
                #undef ACC
                #pragma unroll
                for (int o = 16; o > 0; o >>= 1) {
                    s += __shfl_xor_sync(0xffffffffu, s, o);
                    k += __shfl_xor_sync(0xffffffffu, k, o);
                }
                if (lid == 0) { sredf[tid >> 5] = s; sredk[tid >> 5] = k; }
                __syncthreads();
                if (tid == 0) {
                    float S = 0.0f; int K = 0;
                    #pragma unroll
                    for (int w = 0; w < NWARPS; w++) { S += sredf[w]; K += sredk[w]; }
                    s_tau = (S - 1.0f) / (float)K;
                    s_k = K;
                }
                __syncthreads();
                tau = s_tau;
                int K = s_k;
                if (K == prev) break;
                prev = K;
            }
        }
        __syncthreads();                 // BARRIER 3: s_tau visible
        const float tau = s_tau;
        if (tid == 0) s_cnt = 0;         // next gather is after next BARRIER 1

        // ---- write relu(x - tau) from registers (streaming stores) ----
        c0.x = fmaxf(c0.x - tau, 0.0f); c0.y = fmaxf(c0.y - tau, 0.0f);
        c0.z = fmaxf(c0.z - tau, 0.0f); c0.w = fmaxf(c0.w - tau, 0.0f);
        c1.x = fmaxf(c1.x - tau, 0.0f); c1.y = fmaxf(c1.y - tau, 0.0f);
        c1.z = fmaxf(c1.z - tau, 0.0f); c1.w = fmaxf(c1.w - tau, 0.0f);
        c2.x = fmaxf(c2.x - tau, 0.0f); c2.y = fmaxf(c2.y - tau, 0.0f);
        c2.z = fmaxf(c2.z - tau, 0.0f); c2.w = fmaxf(c2.w - tau, 0.0f);
        c3.x = fmaxf(c3.x - tau, 0.0f); c3.y = fmaxf(c3.y - tau, 0.0f);
        c3.z = fmaxf(c3.z - tau, 0.0f); c3.w = fmaxf(c3.w - tau, 0.0f);
        float4* __restrict__ xout = reinterpret_cast<float4*>(out + (size_t)r * D);
        __stcs(&xout[tid],               c0);
        __stcs(&xout[tid + THREADS],     c1);
        __stcs(&xout[tid + 2 * THREADS], c2);
        __stcs(&xout[tid + 3 * THREADS], c3);

        if (!has_next) break;
        cur ^= 1;
        r = rn;
    }
}

extern "C" void kernel_launch(void* const* d_in, const int* in_sizes, int n_in,
                              void* d_out, int out_size) {
    const float* x = (const float*)d_in[0];
    float* out = (float*)d_out;
    const int rows = in_sizes[0] / D;   // 8192

    const int dyn_smem = 2 * D * (int)sizeof(float);   // 64 KB double buffer
    cudaFuncSetAttribute(sparsemax_kernel,
                         cudaFuncAttributeMaxDynamicSharedMemorySize, dyn_smem);

    int dev = 0;
    cudaGetDevice(&dev);
    int nsm = 148;
    cudaDeviceGetAttribute(&nsm, cudaDevAttrMultiProcessorCount, dev);
    int grid = nsm * 3;                 // 3 CTAs/SM, persistent pipeline
    if (grid > rows) grid = rows;

    sparsemax_kernel<<<grid, THREADS, dyn_smem>>>(x, out, rows);
}